// round 2
// baseline (speedup 1.0000x reference)
#include <cuda_runtime.h>
#include <math.h>

#define T_STEPS 512
#define BATCH   64
#define IN_DIM  1024
#define HID     1024
#define GATES   4096   // 4*HID, gate order i,g,f,o

// Scratch: precomputed input projection wx = x@W + bias, and cell state.
__device__ float g_wx[(size_t)T_STEPS * BATCH * GATES];   // 512 MB
__device__ float g_c[BATCH * HID];

// ---------------------------------------------------------------------------
// SGEMM with bias: g_wx[M,N] = A[M,K] * W[K,N] + bias[N]
// M = T*B = 32768, N = 4096, K = 1024
// 128x128 block tile, BK=8, 256 threads, 8x8 per-thread register tile.
// ---------------------------------------------------------------------------
__global__ __launch_bounds__(256) void sgemm_bias(const float* __restrict__ A,
                                                  const float* __restrict__ W,
                                                  const float* __restrict__ bias)
{
    const int N = GATES, K = IN_DIM;
    __shared__ float As[8][128];
    __shared__ float Bs[8][128];

    int tid  = threadIdx.x;
    int row0 = blockIdx.y * 128;
    int col0 = blockIdx.x * 128;

    // A tile load mapping: 128 rows x 8 k, one float4 per thread
    int ar = tid >> 1;
    int ak = (tid & 1) * 4;
    // W tile load mapping: 8 k x 128 cols, one float4 per thread
    int bk = tid >> 5;
    int bc = (tid & 31) * 4;
    // compute tile coords
    int tcol = (tid & 15) * 8;
    int trow = (tid >> 4) * 8;

    float acc[8][8];
#pragma unroll
    for (int i = 0; i < 8; i++)
#pragma unroll
        for (int j = 0; j < 8; j++) acc[i][j] = 0.f;

    const float* Ap = A + (size_t)(row0 + ar) * K + ak;
    const float* Wp = W + (size_t)bk * N + col0 + bc;

    for (int k0 = 0; k0 < K; k0 += 8) {
        float4 av = *(const float4*)(Ap + k0);
        As[ak + 0][ar] = av.x;
        As[ak + 1][ar] = av.y;
        As[ak + 2][ar] = av.z;
        As[ak + 3][ar] = av.w;
        *(float4*)&Bs[bk][bc] = *(const float4*)(Wp + (size_t)k0 * N);
        __syncthreads();

#pragma unroll
        for (int kk = 0; kk < 8; kk++) {
            float a[8], b[8];
            *(float4*)&a[0] = *(const float4*)&As[kk][trow];
            *(float4*)&a[4] = *(const float4*)&As[kk][trow + 4];
            *(float4*)&b[0] = *(const float4*)&Bs[kk][tcol];
            *(float4*)&b[4] = *(const float4*)&Bs[kk][tcol + 4];
#pragma unroll
            for (int i = 0; i < 8; i++)
#pragma unroll
                for (int j = 0; j < 8; j++)
                    acc[i][j] = fmaf(a[i], b[j], acc[i][j]);
        }
        __syncthreads();
    }

#pragma unroll
    for (int i = 0; i < 8; i++) {
        int r = row0 + trow + i;
#pragma unroll
        for (int j = 0; j < 8; j += 4) {
            float4 o;
            int c = col0 + tcol + j;
            o.x = acc[i][j + 0] + bias[c + 0];
            o.y = acc[i][j + 1] + bias[c + 1];
            o.z = acc[i][j + 2] + bias[c + 2];
            o.w = acc[i][j + 3] + bias[c + 3];
            *(float4*)&g_wx[(size_t)r * N + c] = o;
        }
    }
}

// ---------------------------------------------------------------------------
// Fused LSTM step: v = wx[t] + h_prev @ R, then gates -> h_t, c_t.
// Grid: 128 blocks, each owns 8 h-columns (all 4 gates, all 64 batches).
// 256 threads: tx in [0,32) = (gate, col) pair; ty in [0,8) = batch octet.
// h_prev is read from the output buffer at t-1; t==0 means zeros.
// ---------------------------------------------------------------------------
__global__ __launch_bounds__(256) void lstm_step(int t,
                                                 const float* __restrict__ R,
                                                 float* __restrict__ out_base)
{
    __shared__ float hS[64][68];   // [k][batch], padded for alignment
    __shared__ float rS[64][32];   // [k][(gate,col)]

    int tid = threadIdx.x;
    int tx  = tid & 31;
    int ty  = tid >> 5;
    int hc0 = blockIdx.x * 8;
    int gi  = tx >> 3;
    int gcol = gi * HID + hc0 + (tx & 7);

    const float* wx_t = g_wx + (size_t)t * BATCH * GATES;

    float acc[8] = {0.f, 0.f, 0.f, 0.f, 0.f, 0.f, 0.f, 0.f};

    if (t > 0) {
        const float* hp = out_base + (size_t)(t - 1) * BATCH * HID;
        int kk4  = (tid & 15) * 4;
        int brow = tid >> 4;       // 0..15

        for (int k0 = 0; k0 < IN_DIM; k0 += 64) {
            // stage h_prev chunk transposed: hS[kk][b]
#pragma unroll
            for (int p = 0; p < 4; p++) {
                int b = brow + p * 16;
                float4 hv = *(const float4*)&hp[(size_t)b * HID + k0 + kk4];
                hS[kk4 + 0][b] = hv.x;
                hS[kk4 + 1][b] = hv.y;
                hS[kk4 + 2][b] = hv.z;
                hS[kk4 + 3][b] = hv.w;
            }
            // stage R chunk: rS[kk][tx] = R[k0+kk][gcol]
#pragma unroll
            for (int q = 0; q < 8; q++) {
                int kk = ty + q * 8;
                rS[kk][tx] = R[(size_t)(k0 + kk) * GATES + gcol];
            }
            __syncthreads();

#pragma unroll
            for (int kk = 0; kk < 64; kk++) {
                float rv = rS[kk][tx];
                float4 h0 = *(const float4*)&hS[kk][ty * 8];
                float4 h1 = *(const float4*)&hS[kk][ty * 8 + 4];
                acc[0] = fmaf(h0.x, rv, acc[0]);
                acc[1] = fmaf(h0.y, rv, acc[1]);
                acc[2] = fmaf(h0.z, rv, acc[2]);
                acc[3] = fmaf(h0.w, rv, acc[3]);
                acc[4] = fmaf(h1.x, rv, acc[4]);
                acc[5] = fmaf(h1.y, rv, acc[5]);
                acc[6] = fmaf(h1.z, rv, acc[6]);
                acc[7] = fmaf(h1.w, rv, acc[7]);
            }
            __syncthreads();
        }
    }

    float* h_out = out_base + (size_t)t * BATCH * HID;
#pragma unroll
    for (int i = 0; i < 8; i++) {
        int b = ty * 8 + i;
        float v = acc[i] + wx_t[(size_t)b * GATES + gcol];
        // lanes 0..7 hold gate i; pull g, f, o from lanes +8, +16, +24
        float vg = __shfl_sync(0xffffffffu, v, (tx & 7) + 8);
        float vf = __shfl_sync(0xffffffffu, v, (tx & 7) + 16);
        float vo = __shfl_sync(0xffffffffu, v, (tx & 7) + 24);
        if (tx < 8) {
            float ig = 1.f / (1.f + expf(-v));
            float gg = tanhf(vg);
            float ff = 1.f / (1.f + expf(-vf));
            float oo = 1.f / (1.f + expf(-vo));
            int idx = b * HID + hc0 + tx;
            float cp = (t > 0) ? g_c[idx] : 0.f;
            float cn = ff * cp + ig * gg;
            g_c[idx] = cn;
            h_out[idx] = oo * tanhf(cn);
        }
    }
}

// ---------------------------------------------------------------------------
// Epilogue: h_last = output[T-1], c_last = g_c
// ---------------------------------------------------------------------------
__global__ void finalize(float* __restrict__ out)
{
    int i = blockIdx.x * blockDim.x + threadIdx.x;
    if (i < BATCH * HID) {
        size_t base = (size_t)T_STEPS * BATCH * HID;
        out[base + i] = out[(size_t)(T_STEPS - 1) * BATCH * HID + i];
        out[base + BATCH * HID + i] = g_c[i];
    }
}

extern "C" void kernel_launch(void* const* d_in, const int* in_sizes, int n_in,
                              void* d_out, int out_size)
{
    const float* x    = (const float*)d_in[0];
    const float* Wk   = (const float*)d_in[1];
    const float* Rk   = (const float*)d_in[2];
    const float* bias = (const float*)d_in[3];
    float* out = (float*)d_out;

    dim3 g(GATES / 128, (T_STEPS * BATCH) / 128);
    sgemm_bias<<<g, 256>>>(x, Wk, bias);

    for (int t = 0; t < T_STEPS; t++)
        lstm_step<<<HID / 8, 256>>>(t, Rk, out);

    finalize<<<(BATCH * HID + 255) / 256, 256>>>(out);
}

// round 4
// speedup vs baseline: 1.8356x; 1.8356x over previous
#include <cuda_runtime.h>
#include <cuda_bf16.h>
#include <math.h>
#include <stdint.h>

#define T_STEPS 512
#define BATCH   64
#define IN_DIM  1024
#define HID     1024
#define GATES   4096   // 4*HID, gate order i,g,f,o

// ---------------- device scratch ----------------
__device__ float g_wx[(size_t)T_STEPS * BATCH * GATES];   // 512 MB
__device__ float g_c[BATCH * HID];

__device__ __nv_bfloat16 g_xhi[(size_t)T_STEPS * BATCH * IN_DIM];
__device__ __nv_bfloat16 g_xlo[(size_t)T_STEPS * BATCH * IN_DIM];
__device__ __nv_bfloat16 g_Wthi[(size_t)GATES * IN_DIM];   // transposed [N][K]
__device__ __nv_bfloat16 g_Wtlo[(size_t)GATES * IN_DIM];
__device__ __nv_bfloat16 g_Rthi[(size_t)GATES * HID];      // transposed [N][K]
__device__ __nv_bfloat16 g_Rtlo[(size_t)GATES * HID];
__device__ __nv_bfloat16 g_hhi[2][BATCH * HID];            // ping-pong h in bf16 hi/lo
__device__ __nv_bfloat16 g_hlo[2][BATCH * HID];

// ---------------- mma.m16n8k16 bf16 helper ----------------
// Fragment layout (g = lane>>2, t = lane&3):
//  A row-major 16x16: a0=A[g][2t..], a1=A[g+8][2t..], a2=A[g][2t+8..], a3=A[g+8][2t+8..]
//  B col-major 16x8 stored here as Bt[n][k]: b0=Bt[g][2t..], b1=Bt[g][2t+8..]
//  C 16x8 f32: c0=C[g][2t], c1=C[g][2t+1], c2=C[g+8][2t], c3=C[g+8][2t+1]
__device__ __forceinline__ void mma16816(float* c, const uint32_t* a, const uint32_t* b)
{
    asm volatile(
        "mma.sync.aligned.m16n8k16.row.col.f32.bf16.bf16.f32 "
        "{%0,%1,%2,%3}, {%4,%5,%6,%7}, {%8,%9}, {%0,%1,%2,%3};"
        : "+f"(c[0]), "+f"(c[1]), "+f"(c[2]), "+f"(c[3])
        : "r"(a[0]), "r"(a[1]), "r"(a[2]), "r"(a[3]), "r"(b[0]), "r"(b[1]));
}

__device__ __forceinline__ void split_bf16(float v, __nv_bfloat16& hi, __nv_bfloat16& lo)
{
    hi = __float2bfloat16_rn(v);
    lo = __float2bfloat16_rn(v - __bfloat162float(hi));
}

// ---------------- conversion kernels ----------------
// All write targets are referenced directly from DEVICE code (never passed as
// kernel args from host — __device__ symbols are invalid host-side).
__global__ void convert_x(const float* __restrict__ x)
{
    size_t i = (size_t)blockIdx.x * blockDim.x + threadIdx.x;
    if (i < (size_t)T_STEPS * BATCH * IN_DIM) {
        __nv_bfloat16 hi, lo;
        split_bf16(x[i], hi, lo);
        g_xhi[i] = hi;
        g_xlo[i] = lo;
    }
}

// src [K=1024][N=4096] row-major -> g_Wt{hi,lo} [N][K] bf16 (transposed)
__global__ void convert_W(const float* __restrict__ src)
{
    __shared__ float tile[32][33];
    int n0 = blockIdx.x * 32, k0 = blockIdx.y * 32;
    int tx = threadIdx.x, ty = threadIdx.y;   // 32 x 8
#pragma unroll
    for (int i = 0; i < 32; i += 8)
        tile[ty + i][tx] = src[(size_t)(k0 + ty + i) * GATES + n0 + tx];
    __syncthreads();
#pragma unroll
    for (int i = 0; i < 32; i += 8) {
        float v = tile[tx][ty + i];           // = src[k0+tx][n0+ty+i]
        size_t o = (size_t)(n0 + ty + i) * IN_DIM + k0 + tx;
        __nv_bfloat16 hi, lo;
        split_bf16(v, hi, lo);
        g_Wthi[o] = hi;
        g_Wtlo[o] = lo;
    }
}

// src [K=1024][N=4096] row-major -> g_Rt{hi,lo} [N][K] bf16 (transposed)
__global__ void convert_R(const float* __restrict__ src)
{
    __shared__ float tile[32][33];
    int n0 = blockIdx.x * 32, k0 = blockIdx.y * 32;
    int tx = threadIdx.x, ty = threadIdx.y;   // 32 x 8
#pragma unroll
    for (int i = 0; i < 32; i += 8)
        tile[ty + i][tx] = src[(size_t)(k0 + ty + i) * GATES + n0 + tx];
    __syncthreads();
#pragma unroll
    for (int i = 0; i < 32; i += 8) {
        float v = tile[tx][ty + i];
        size_t o = (size_t)(n0 + ty + i) * HID + k0 + tx;
        __nv_bfloat16 hi, lo;
        split_bf16(v, hi, lo);
        g_Rthi[o] = hi;
        g_Rtlo[o] = lo;
    }
}

// ---------------- wx GEMM: g_wx[M,N] = x@W + bias, split-bf16 mma ----------------
// M=32768, N=4096, K=1024. CTA tile 128x128, K-chunk 32, 8 warps (2m x 4n),
// warp tile 64x32 (4 m16 x 4 n8).
#define WXS 40   // smem k-stride (32 + 8 pad) in bf16 elems
__global__ __launch_bounds__(256) void wx_mma(const float* __restrict__ bias)
{
    __shared__ __align__(16) __nv_bfloat16 Ah[128 * WXS], Al[128 * WXS];
    __shared__ __align__(16) __nv_bfloat16 Bh[128 * WXS], Bl[128 * WXS];

    int tid  = threadIdx.x;
    int lane = tid & 31, w = tid >> 5;
    int g = lane >> 2, tq = lane & 3;
    size_t m0 = (size_t)blockIdx.y * 128;
    int n0 = blockIdx.x * 128;
    int wm = w & 1, wn = w >> 1;

    float acc[4][4][4];
#pragma unroll
    for (int mt = 0; mt < 4; mt++)
#pragma unroll
        for (int nt = 0; nt < 4; nt++)
#pragma unroll
            for (int r = 0; r < 4; r++) acc[mt][nt][r] = 0.f;

    for (int kc = 0; kc < 32; kc++) {
        int k0 = kc * 32;
#pragma unroll
        for (int rep = 0; rep < 2; rep++) {
            int id = tid + rep * 256;          // 0..511
            int row = id >> 2, seg = id & 3;   // 128 rows x 4 x 16B
            size_t asrc = (m0 + row) * IN_DIM + k0 + seg * 8;
            size_t bsrc = (size_t)(n0 + row) * IN_DIM + k0 + seg * 8;
            *(uint4*)&Ah[row * WXS + seg * 8] = *(const uint4*)&g_xhi[asrc];
            *(uint4*)&Al[row * WXS + seg * 8] = *(const uint4*)&g_xlo[asrc];
            *(uint4*)&Bh[row * WXS + seg * 8] = *(const uint4*)&g_Wthi[bsrc];
            *(uint4*)&Bl[row * WXS + seg * 8] = *(const uint4*)&g_Wtlo[bsrc];
        }
        __syncthreads();

#pragma unroll
        for (int ks = 0; ks < 2; ks++) {
            int ko = ks * 16;
            uint32_t bh[4][2], bl[4][2];
#pragma unroll
            for (int nt = 0; nt < 4; nt++) {
                int r = wn * 32 + nt * 8 + g;
                bh[nt][0] = *(const uint32_t*)&Bh[r * WXS + ko + 2 * tq];
                bh[nt][1] = *(const uint32_t*)&Bh[r * WXS + ko + 2 * tq + 8];
                bl[nt][0] = *(const uint32_t*)&Bl[r * WXS + ko + 2 * tq];
                bl[nt][1] = *(const uint32_t*)&Bl[r * WXS + ko + 2 * tq + 8];
            }
#pragma unroll
            for (int mt = 0; mt < 4; mt++) {
                int r0 = wm * 64 + mt * 16 + g, r1 = r0 + 8;
                uint32_t ah[4], al[4];
                ah[0] = *(const uint32_t*)&Ah[r0 * WXS + ko + 2 * tq];
                ah[1] = *(const uint32_t*)&Ah[r1 * WXS + ko + 2 * tq];
                ah[2] = *(const uint32_t*)&Ah[r0 * WXS + ko + 2 * tq + 8];
                ah[3] = *(const uint32_t*)&Ah[r1 * WXS + ko + 2 * tq + 8];
                al[0] = *(const uint32_t*)&Al[r0 * WXS + ko + 2 * tq];
                al[1] = *(const uint32_t*)&Al[r1 * WXS + ko + 2 * tq];
                al[2] = *(const uint32_t*)&Al[r0 * WXS + ko + 2 * tq + 8];
                al[3] = *(const uint32_t*)&Al[r1 * WXS + ko + 2 * tq + 8];
#pragma unroll
                for (int nt = 0; nt < 4; nt++) {
                    mma16816(acc[mt][nt], ah, bh[nt]);
                    mma16816(acc[mt][nt], ah, bl[nt]);
                    mma16816(acc[mt][nt], al, bh[nt]);
                }
            }
        }
        __syncthreads();
    }

#pragma unroll
    for (int mt = 0; mt < 4; mt++) {
        size_t row = m0 + wm * 64 + mt * 16 + g;
#pragma unroll
        for (int nt = 0; nt < 4; nt++) {
            int col = n0 + wn * 32 + nt * 8 + 2 * tq;
            g_wx[row * GATES + col]           = acc[mt][nt][0] + bias[col];
            g_wx[row * GATES + col + 1]       = acc[mt][nt][1] + bias[col + 1];
            g_wx[(row + 8) * GATES + col]     = acc[mt][nt][2] + bias[col];
            g_wx[(row + 8) * GATES + col + 1] = acc[mt][nt][3] + bias[col + 1];
        }
    }
}

// ---------------- fused LSTM step (tensor core) ----------------
// v[64,4096] = wx[t] + h_prev @ R. Grid 128: CTA owns 8 h-cols x 4 gates
// (n8 tile nt == gate nt, col group hc0..hc0+7). 4 warps, warp = 16 batch rows.
// C-fragment => all 4 gates for one (b,col) land in the same lane: no shuffles.
#define STS 72   // smem k-stride (64 + 8 pad) in bf16 elems
__global__ __launch_bounds__(128) void lstm_step_mma(int t, float* __restrict__ out_base)
{
    __shared__ __align__(16) __nv_bfloat16 Hh[64 * STS], Hl[64 * STS];
    __shared__ __align__(16) __nv_bfloat16 Rh[32 * STS], Rl[32 * STS];

    int tid  = threadIdx.x;
    int lane = tid & 31, w = tid >> 5;
    int g = lane >> 2, tq = lane & 3;
    int hc0 = blockIdx.x * 8;

    float acc[4][4];
#pragma unroll
    for (int nt = 0; nt < 4; nt++)
#pragma unroll
        for (int r = 0; r < 4; r++) acc[nt][r] = 0.f;

    if (t > 0) {
        int pb = (t - 1) & 1;
        const __nv_bfloat16* hhi = g_hhi[pb];
        const __nv_bfloat16* hlo = g_hlo[pb];

        for (int kc = 0; kc < 16; kc++) {
            int k0 = kc * 64;
            // stage h: 64 rows x 64 k (8 x 16B segs per row)
#pragma unroll
            for (int rep = 0; rep < 4; rep++) {
                int id = tid + rep * 128;       // 0..511
                int row = id >> 3, seg = id & 7;
                size_t src = (size_t)row * HID + k0 + seg * 8;
                *(uint4*)&Hh[row * STS + seg * 8] = *(const uint4*)&hhi[src];
                *(uint4*)&Hl[row * STS + seg * 8] = *(const uint4*)&hlo[src];
            }
            // stage R: 32 rows (gate*8+c8) x 64 k
#pragma unroll
            for (int rep = 0; rep < 2; rep++) {
                int id = tid + rep * 128;       // 0..255
                int row = id >> 3, seg = id & 7;
                int gate = row >> 3, c8 = row & 7;
                size_t src = (size_t)(gate * HID + hc0 + c8) * HID + k0 + seg * 8;
                *(uint4*)&Rh[row * STS + seg * 8] = *(const uint4*)&g_Rthi[src];
                *(uint4*)&Rl[row * STS + seg * 8] = *(const uint4*)&g_Rtlo[src];
            }
            __syncthreads();

#pragma unroll
            for (int ks = 0; ks < 4; ks++) {
                int ko = ks * 16;
                int r0 = w * 16 + g, r1 = r0 + 8;
                uint32_t ah[4], al[4];
                ah[0] = *(const uint32_t*)&Hh[r0 * STS + ko + 2 * tq];
                ah[1] = *(const uint32_t*)&Hh[r1 * STS + ko + 2 * tq];
                ah[2] = *(const uint32_t*)&Hh[r0 * STS + ko + 2 * tq + 8];
                ah[3] = *(const uint32_t*)&Hh[r1 * STS + ko + 2 * tq + 8];
                al[0] = *(const uint32_t*)&Hl[r0 * STS + ko + 2 * tq];
                al[1] = *(const uint32_t*)&Hl[r1 * STS + ko + 2 * tq];
                al[2] = *(const uint32_t*)&Hl[r0 * STS + ko + 2 * tq + 8];
                al[3] = *(const uint32_t*)&Hl[r1 * STS + ko + 2 * tq + 8];
#pragma unroll
                for (int nt = 0; nt < 4; nt++) {
                    int rr = nt * 8 + g;
                    uint32_t bh[2], bl[2];
                    bh[0] = *(const uint32_t*)&Rh[rr * STS + ko + 2 * tq];
                    bh[1] = *(const uint32_t*)&Rh[rr * STS + ko + 2 * tq + 8];
                    bl[0] = *(const uint32_t*)&Rl[rr * STS + ko + 2 * tq];
                    bl[1] = *(const uint32_t*)&Rl[rr * STS + ko + 2 * tq + 8];
                    mma16816(acc[nt], ah, bh);
                    mma16816(acc[nt], ah, bl);
                    mma16816(acc[nt], al, bh);
                }
            }
            __syncthreads();
        }
    }

    // epilogue: gates, cell update, h writes (fp32 + bf16 hi/lo ping-pong)
    const float* wx_t = g_wx + (size_t)t * BATCH * GATES;
    float* h_out = out_base + (size_t)t * BATCH * HID;
    int cb = t & 1;
#pragma unroll
    for (int j = 0; j < 4; j++) {
        int brow = w * 16 + g + ((j >> 1) * 8);
        int cofs = 2 * tq + (j & 1);
        int col  = hc0 + cofs;
        const float* wb = wx_t + (size_t)brow * GATES;
        float vi = acc[0][j] + wb[0 * HID + col];
        float vg = acc[1][j] + wb[1 * HID + col];
        float vf = acc[2][j] + wb[2 * HID + col];
        float vo = acc[3][j] + wb[3 * HID + col];
        float ii = 1.f / (1.f + expf(-vi));
        float gg = tanhf(vg);
        float ff = 1.f / (1.f + expf(-vf));
        float oo = 1.f / (1.f + expf(-vo));
        int idx = brow * HID + col;
        float cp = (t > 0) ? g_c[idx] : 0.f;
        float cn = ff * cp + ii * gg;
        g_c[idx] = cn;
        float h = oo * tanhf(cn);
        h_out[idx] = h;
        __nv_bfloat16 hi, lo;
        split_bf16(h, hi, lo);
        g_hhi[cb][idx] = hi;
        g_hlo[cb][idx] = lo;
    }
}

// ---------------- epilogue: h_last, c_last ----------------
__global__ void finalize(float* __restrict__ out)
{
    int i = blockIdx.x * blockDim.x + threadIdx.x;
    if (i < BATCH * HID) {
        size_t base = (size_t)T_STEPS * BATCH * HID;
        out[base + i] = out[(size_t)(T_STEPS - 1) * BATCH * HID + i];
        out[base + BATCH * HID + i] = g_c[i];
    }
}

extern "C" void kernel_launch(void* const* d_in, const int* in_sizes, int n_in,
                              void* d_out, int out_size)
{
    const float* x    = (const float*)d_in[0];
    const float* Wk   = (const float*)d_in[1];
    const float* Rk   = (const float*)d_in[2];
    const float* bias = (const float*)d_in[3];
    float* out = (float*)d_out;

    size_t nx = (size_t)T_STEPS * BATCH * IN_DIM;
    convert_x<<<(unsigned)((nx + 255) / 256), 256>>>(x);
    convert_W<<<dim3(GATES / 32, IN_DIM / 32), dim3(32, 8)>>>(Wk);
    convert_R<<<dim3(GATES / 32, HID / 32), dim3(32, 8)>>>(Rk);

    wx_mma<<<dim3(GATES / 128, (T_STEPS * BATCH) / 128), 256>>>(bias);

    for (int t = 0; t < T_STEPS; t++)
        lstm_step_mma<<<HID / 8, 128>>>(t, out);

    finalize<<<(BATCH * HID + 255) / 256, 256>>>(out);
}